// round 2
// baseline (speedup 1.0000x reference)
#include <cuda_runtime.h>
#include <math.h>

#define BATCH 4
#define SEQ 2048
#define HIDDEN 1024
#define NHEAD 16
#define DHEAD 64
#define MTOT (BATCH*SEQ)      // 8192
#define NTOT (3*HIDDEN)       // 3072
#define KTOT HIDDEN           // 1024

// Scratch (device globals: no allocation allowed in kernel_launch)
__device__ float g_q[(size_t)MTOT*HIDDEN];
__device__ float g_k[(size_t)MTOT*HIDDEN];
__device__ float g_v[(size_t)MTOT*HIDDEN];
__device__ float g_cs[SEQ*32*2];   // cos/sin table [s][j][2]

// ---------------------------------------------------------------------------
// RoPE cos/sin table (double-precision generation to match jax fp32 pipeline)
// ---------------------------------------------------------------------------
__global__ void rope_table_kernel() {
    int idx = blockIdx.x * blockDim.x + threadIdx.x;
    if (idx >= SEQ * 32) return;
    int s = idx >> 5;
    int j = idx & 31;
    float invf = (float)(1.0 / pow(10000.0, (double)j / 32.0));
    float ang  = (float)s * invf;                 // fp32 rounding like jax
    g_cs[idx*2 + 0] = (float)cos((double)ang);
    g_cs[idx*2 + 1] = (float)sin((double)ang);
}

// ---------------------------------------------------------------------------
// QKV projection GEMM: C[m][n] = sum_k A[m][k]*W[n][k] + bias[n]
// 128x128 tile, BK=8, 256 threads, 8x8 per thread, double-buffered smem.
// Writes directly into g_q / g_k / g_v (n-section uniform per block).
// ---------------------------------------------------------------------------
__global__ __launch_bounds__(256) void qkv_gemm_kernel(
        const float* __restrict__ A, const float* __restrict__ W,
        const float* __restrict__ bias) {
    __shared__ float Ast[2][8][132];
    __shared__ float Wst[2][8][132];
    const int tid  = threadIdx.x;
    const int m0   = blockIdx.y * 128;
    const int n0   = blockIdx.x * 128;
    const int row0 = (tid >> 4) * 8;
    const int col0 = (tid & 15) * 8;
    const int lr   = tid >> 1;
    const int lk   = (tid & 1) * 4;

    const float* Ap = A + (size_t)(m0 + lr) * KTOT + lk;
    const float* Wp = W + (size_t)(n0 + lr) * KTOT + lk;

    float acc[8][8];
    #pragma unroll
    for (int i = 0; i < 8; i++)
        #pragma unroll
        for (int j = 0; j < 8; j++) acc[i][j] = 0.0f;

    float4 ra = *(const float4*)Ap;
    float4 rw = *(const float4*)Wp;
    #pragma unroll
    for (int j = 0; j < 4; j++) {
        Ast[0][lk + j][lr] = ((const float*)&ra)[j];
        Wst[0][lk + j][lr] = ((const float*)&rw)[j];
    }
    __syncthreads();

    const int NKT = KTOT / 8;   // 128
    for (int kt = 0; kt < NKT; kt++) {
        const int cur = kt & 1;
        if (kt + 1 < NKT) {
            ra = *(const float4*)(Ap + (kt + 1) * 8);
            rw = *(const float4*)(Wp + (kt + 1) * 8);
        }
        #pragma unroll
        for (int kk = 0; kk < 8; kk++) {
            float a[8], b[8];
            *(float4*)&a[0] = *(const float4*)&Ast[cur][kk][row0];
            *(float4*)&a[4] = *(const float4*)&Ast[cur][kk][row0 + 4];
            *(float4*)&b[0] = *(const float4*)&Wst[cur][kk][col0];
            *(float4*)&b[4] = *(const float4*)&Wst[cur][kk][col0 + 4];
            #pragma unroll
            for (int i = 0; i < 8; i++)
                #pragma unroll
                for (int j = 0; j < 8; j++)
                    acc[i][j] += a[i] * b[j];
        }
        if (kt + 1 < NKT) {
            const int nxt = cur ^ 1;
            #pragma unroll
            for (int j = 0; j < 4; j++) {
                Ast[nxt][lk + j][lr] = ((const float*)&ra)[j];
                Wst[nxt][lk + j][lr] = ((const float*)&rw)[j];
            }
        }
        __syncthreads();
    }

    // Epilogue: bias add, route to q/k/v
    const int sec = n0 / HIDDEN;                  // uniform per block
    float* dst = (sec == 0) ? g_q : (sec == 1) ? g_k : g_v;
    const int nc = (n0 % HIDDEN) + col0;
    #pragma unroll
    for (int i = 0; i < 8; i++) {
        const size_t m = (size_t)(m0 + row0 + i);
        #pragma unroll
        for (int j = 0; j < 8; j += 4) {
            const float4 bv = *(const float4*)&bias[n0 + col0 + j];
            float4 v;
            v.x = acc[i][j + 0] + bv.x;
            v.y = acc[i][j + 1] + bv.y;
            v.z = acc[i][j + 2] + bv.z;
            v.w = acc[i][j + 3] + bv.w;
            *(float4*)&dst[m * HIDDEN + nc + j] = v;
        }
    }
}

// ---------------------------------------------------------------------------
// In-place RoPE on g_q and g_k
// ---------------------------------------------------------------------------
__global__ void rope_kernel() {
    const int tot = MTOT * NHEAD * 32;
    int idx = blockIdx.x * blockDim.x + threadIdx.x;
    if (idx >= tot) return;
    const int j = idx & 31;
    const int h = (idx >> 5) & 15;
    const int m = idx >> 9;
    const int s = m & (SEQ - 1);
    const float c  = g_cs[(s * 32 + j) * 2 + 0];
    const float sn = g_cs[(s * 32 + j) * 2 + 1];
    const size_t base = (size_t)m * HIDDEN + h * DHEAD + j;

    float q1 = g_q[base], q2 = g_q[base + 32];
    g_q[base]      = q1 * c - q2 * sn;
    g_q[base + 32] = q2 * c + q1 * sn;

    float k1 = g_k[base], k2 = g_k[base + 32];
    g_k[base]      = k1 * c - k2 * sn;
    g_k[base + 32] = k2 * c + k1 * sn;
}

// ---------------------------------------------------------------------------
// Flash attention (fp32 SIMT): 64-row Q tile per block, 64-key KV tiles.
// 128 threads (8 ty x 16 tx), thread tile 8q x 4(k|d).
// Smem layouts chosen for conflict-free float4 loads in the hot loops:
//   Qst/Kst: d-major [dd][row] (transposed at load; load-mapping makes the
//   transpose writes conflict-free), Pst: [q][68], Vs: [k][68].
// ---------------------------------------------------------------------------
#define ATTN_SMEM ((4096 + 4096 + 64*68 + 64*68) * 4)

__global__ __launch_bounds__(128) void attn_kernel(float* __restrict__ out) {
    extern __shared__ float sm[];
    float* Qst = sm;                  // [64][64]  Qst[dd*64 + q]
    float* Kst = sm + 4096;           // [64][64]  Kst[dd*64 + k]
    float* Pst = sm + 8192;           // [64][68]  Pst[q*68 + k]
    float* Vs  = sm + 8192 + 64*68;   // [64][68]  Vs[k*68 + dd]

    const int tid = threadIdx.x;
    const int ty  = tid >> 4;         // 0..7
    const int tx  = tid & 15;         // 0..15
    const int bh  = blockIdx.y;
    const int b   = bh >> 4;
    const int h   = bh & 15;
    const int q0  = blockIdx.x * 64;
    const size_t rowbase = (size_t)b * SEQ;
    const float* Qg = g_q + rowbase * HIDDEN + h * DHEAD;
    const float* Kg = g_k + rowbase * HIDDEN + h * DHEAD;
    const float* Vg = g_v + rowbase * HIDDEN + h * DHEAD;

    const int lrow = tid & 63;        // load mapping (conflict-free transpose)
    const int half = tid >> 6;

    // Load Q tile (transposed, pre-scaled by 1/sqrt(64))
    #pragma unroll
    for (int it = 0; it < 8; it++) {
        const int dd = (it * 2 + half) * 4;
        float4 v = *(const float4*)&Qg[(size_t)(q0 + lrow) * HIDDEN + dd];
        Qst[(dd + 0) * 64 + lrow] = v.x * 0.125f;
        Qst[(dd + 1) * 64 + lrow] = v.y * 0.125f;
        Qst[(dd + 2) * 64 + lrow] = v.z * 0.125f;
        Qst[(dd + 3) * 64 + lrow] = v.w * 0.125f;
    }

    float m_i[8], l_i[8], o[8][4];
    #pragma unroll
    for (int i = 0; i < 8; i++) {
        m_i[i] = -INFINITY; l_i[i] = 0.0f;
        #pragma unroll
        for (int j = 0; j < 4; j++) o[i][j] = 0.0f;
    }

    for (int kt = 0; kt < SEQ / 64; kt++) {
        __syncthreads();   // prior GEMM2 done reading Pst/Vs

        // Load K tile (transposed)
        #pragma unroll
        for (int it = 0; it < 8; it++) {
            const int dd = (it * 2 + half) * 4;
            float4 v = *(const float4*)&Kg[(size_t)(kt * 64 + lrow) * HIDDEN + dd];
            Kst[(dd + 0) * 64 + lrow] = v.x;
            Kst[(dd + 1) * 64 + lrow] = v.y;
            Kst[(dd + 2) * 64 + lrow] = v.z;
            Kst[(dd + 3) * 64 + lrow] = v.w;
        }
        // Load V tile (natural)
        #pragma unroll
        for (int it = 0; it < 8; it++) {
            const int idx = it * 128 + tid;
            const int r = idx >> 4, c = (idx & 15) * 4;
            *(float4*)&Vs[r * 68 + c] =
                *(const float4*)&Vg[(size_t)(kt * 64 + r) * HIDDEN + c];
        }
        __syncthreads();

        // GEMM1: S = Q K^T (pre-scaled)
        float s[8][4];
        #pragma unroll
        for (int i = 0; i < 8; i++)
            #pragma unroll
            for (int j = 0; j < 4; j++) s[i][j] = 0.0f;

        #pragma unroll 8
        for (int dd = 0; dd < 64; dd++) {
            float a[8], bb[4];
            *(float4*)&a[0]  = *(const float4*)&Qst[dd * 64 + ty * 8];
            *(float4*)&a[4]  = *(const float4*)&Qst[dd * 64 + ty * 8 + 4];
            *(float4*)&bb[0] = *(const float4*)&Kst[dd * 64 + tx * 4];
            #pragma unroll
            for (int i = 0; i < 8; i++)
                #pragma unroll
                for (int j = 0; j < 4; j++)
                    s[i][j] += a[i] * bb[j];
        }

        // Online softmax update (row stats across 16 tx lanes via shfl)
        #pragma unroll
        for (int i = 0; i < 8; i++) {
            float mx = fmaxf(fmaxf(s[i][0], s[i][1]), fmaxf(s[i][2], s[i][3]));
            #pragma unroll
            for (int off = 8; off >= 1; off >>= 1)
                mx = fmaxf(mx, __shfl_xor_sync(0xffffffffu, mx, off));
            const float mnew  = fmaxf(m_i[i], mx);
            const float alpha = expf(m_i[i] - mnew);
            float rs = 0.0f;
            #pragma unroll
            for (int j = 0; j < 4; j++) {
                float p = expf(s[i][j] - mnew);
                s[i][j] = p;
                rs += p;
            }
            #pragma unroll
            for (int off = 8; off >= 1; off >>= 1)
                rs += __shfl_xor_sync(0xffffffffu, rs, off);
            l_i[i] = l_i[i] * alpha + rs;
            m_i[i] = mnew;
            #pragma unroll
            for (int j = 0; j < 4; j++) o[i][j] *= alpha;
            *(float4*)&Pst[(ty * 8 + i) * 68 + tx * 4] = *(float4*)&s[i][0];
        }
        __syncthreads();

        // GEMM2: O += P V
        #pragma unroll 8
        for (int kk = 0; kk < 64; kk++) {
            float bb[4];
            *(float4*)&bb[0] = *(const float4*)&Vs[kk * 68 + tx * 4];
            #pragma unroll
            for (int i = 0; i < 8; i++) {
                const float a = Pst[(ty * 8 + i) * 68 + kk];
                #pragma unroll
                for (int j = 0; j < 4; j++)
                    o[i][j] += a * bb[j];
            }
        }
    }

    // Normalize and write
    #pragma unroll
    for (int i = 0; i < 8; i++) {
        const float inv = 1.0f / l_i[i];
        float4 v;
        v.x = o[i][0] * inv; v.y = o[i][1] * inv;
        v.z = o[i][2] * inv; v.w = o[i][3] * inv;
        const size_t row = rowbase + q0 + ty * 8 + i;
        *(float4*)&out[row * HIDDEN + h * DHEAD + tx * 4] = v;
    }
}

// ---------------------------------------------------------------------------
extern "C" void kernel_launch(void* const* d_in, const int* in_sizes, int n_in,
                              void* d_out, int out_size) {
    const float* hidden = (const float*)d_in[0];
    const float* wqkv   = (const float*)d_in[1];
    const float* bqkv   = (const float*)d_in[2];
    float* out = (float*)d_out;

    cudaFuncSetAttribute(attn_kernel,
                         cudaFuncAttributeMaxDynamicSharedMemorySize, ATTN_SMEM);

    rope_table_kernel<<<(SEQ * 32 + 255) / 256, 256>>>();

    dim3 ggrid(NTOT / 128, MTOT / 128);
    qkv_gemm_kernel<<<ggrid, 256>>>(hidden, wqkv, bqkv);

    const int rtot = MTOT * NHEAD * 32;
    rope_kernel<<<rtot / 256, 256>>>();

    dim3 agrid(SEQ / 64, BATCH * NHEAD);
    attn_kernel<<<agrid, 128, ATTN_SMEM>>>(out);
}

// round 4
// speedup vs baseline: 1.3093x; 1.3093x over previous
#include <cuda_runtime.h>
#include <cuda_bf16.h>
#include <math.h>
#include <stdint.h>

#define BATCH 4
#define SEQ 2048
#define HIDDEN 1024
#define NHEAD 16
#define DHEAD 64
#define MTOT (BATCH*SEQ)      // 8192
#define NTOT (3*HIDDEN)       // 3072
#define KTOT HIDDEN           // 1024

// ---------------------------------------------------------------------------
// Scratch (device globals: no allocation allowed)
// ---------------------------------------------------------------------------
__device__ float g_q[(size_t)MTOT*HIDDEN];
__device__ float g_k[(size_t)MTOT*HIDDEN];
__device__ float g_v[(size_t)MTOT*HIDDEN];
__device__ float g_cs[SEQ*32*2];   // cos/sin table [s][j][2]
__device__ __nv_bfloat16 g_ahi[(size_t)MTOT*KTOT];
__device__ __nv_bfloat16 g_alo[(size_t)MTOT*KTOT];
__device__ __nv_bfloat16 g_whi[(size_t)NTOT*KTOT];
__device__ __nv_bfloat16 g_wlo[(size_t)NTOT*KTOT];

// ---------------------------------------------------------------------------
// PTX helpers (plain sm_80-era PTX: compiles on non-'a' targets)
// ---------------------------------------------------------------------------
__device__ __forceinline__ uint32_t smem_u32(const void* p) {
    uint32_t a;
    asm("{ .reg .u64 t; cvta.to.shared.u64 t, %1; cvt.u32.u64 %0, t; }"
        : "=r"(a) : "l"(p));
    return a;
}
#define CP_ASYNC16(dst, src) \
    asm volatile("cp.async.cg.shared.global [%0], [%1], 16;" \
        :: "r"(dst), "l"(src))
#define CP_COMMIT() asm volatile("cp.async.commit_group;" ::: "memory")
#define CP_WAIT(n)  asm volatile("cp.async.wait_group %0;" :: "n"(n) : "memory")

#define LDMATRIX_X4(r0, r1, r2, r3, addr) \
    asm volatile("ldmatrix.sync.aligned.m8n8.x4.shared.b16 {%0,%1,%2,%3}, [%4];" \
        : "=r"(r0), "=r"(r1), "=r"(r2), "=r"(r3) : "r"(addr))

#define MMA_BF16(d, a, b) \
    asm volatile("mma.sync.aligned.m16n8k16.row.col.f32.bf16.bf16.f32 " \
        "{%0,%1,%2,%3}, {%4,%5,%6,%7}, {%8,%9}, {%0,%1,%2,%3};" \
        : "+f"((d)[0]), "+f"((d)[1]), "+f"((d)[2]), "+f"((d)[3]) \
        : "r"((a)[0]), "r"((a)[1]), "r"((a)[2]), "r"((a)[3]), \
          "r"((b)[0]), "r"((b)[1]))

// ---------------------------------------------------------------------------
// RoPE cos/sin table
// ---------------------------------------------------------------------------
__global__ void rope_table_kernel() {
    int idx = blockIdx.x * blockDim.x + threadIdx.x;
    if (idx >= SEQ * 32) return;
    int s = idx >> 5;
    int j = idx & 31;
    float invf = (float)(1.0 / pow(10000.0, (double)j / 32.0));
    float ang  = (float)s * invf;
    g_cs[idx*2 + 0] = (float)cos((double)ang);
    g_cs[idx*2 + 1] = (float)sin((double)ang);
}

// ---------------------------------------------------------------------------
// fp32 -> (bf16 hi, bf16 lo) split conversion
// ---------------------------------------------------------------------------
__global__ void convert_split_kernel(const float* __restrict__ src,
                                     __nv_bfloat16* __restrict__ hi,
                                     __nv_bfloat16* __restrict__ lo, int n4) {
    int i = blockIdx.x * blockDim.x + threadIdx.x;
    if (i >= n4) return;
    float4 v = ((const float4*)src)[i];
    __nv_bfloat16 h[4], l[4];
    const float* f = (const float*)&v;
    #pragma unroll
    for (int j = 0; j < 4; j++) {
        h[j] = __float2bfloat16(f[j]);
        l[j] = __float2bfloat16(f[j] - __bfloat162float(h[j]));
    }
    ((uint2*)hi)[i] = *(const uint2*)h;
    ((uint2*)lo)[i] = *(const uint2*)l;
}

// ---------------------------------------------------------------------------
// QKV GEMM via mma.sync bf16 (split): D = Ah*Bh + Ah*Bl + Al*Bh (+bias)
// CTA 128x128, BK=32, 8 warps (4m x 2n), warp tile 32x64.
// Smem rows strided 40 bf16 (80B): (row*5) mod 8 hits all 16B bank groups
// -> conflict-free ldmatrix phases. cp.async double-buffered stages.
// ---------------------------------------------------------------------------
#define GT_TILE  10240                 // one 128x40 bf16 tile, bytes
#define GT_STAGE (4*GT_TILE)           // Ah,Al,Bh,Bl
#define GEMM_SMEM (2*GT_STAGE)         // 81920 bytes

__global__ __launch_bounds__(256) void qkv_gemm_mma(const float* __restrict__ bias) {
    extern __shared__ char smg[];
    const uint32_t smb = smem_u32(smg);
    const int tid  = threadIdx.x;
    const int lane = tid & 31;
    const int wid  = tid >> 5;
    const int wr   = wid & 3;          // warp m index (0..3)
    const int wc   = wid >> 2;         // warp n index (0..1)
    const int n0   = blockIdx.x * 128;
    const int m0   = blockIdx.y * 128;

    // ---- global load mapping: thread -> (row, 32B segment) of each tile
    const int lrow = tid >> 1;                 // 0..127
    const int lcol = (tid & 1) * 16;           // bf16 element col: 0 or 16
    const __nv_bfloat16* gAh = g_ahi + (size_t)(m0 + lrow) * KTOT + lcol;
    const __nv_bfloat16* gAl = g_alo + (size_t)(m0 + lrow) * KTOT + lcol;
    const __nv_bfloat16* gBh = g_whi + (size_t)(n0 + lrow) * KTOT + lcol;
    const __nv_bfloat16* gBl = g_wlo + (size_t)(n0 + lrow) * KTOT + lcol;
    const uint32_t dOff = (uint32_t)(lrow * 80 + lcol * 2);

    #define LOAD_STAGE(st, kc) do { \
        const uint32_t sb = smb + (st) * GT_STAGE + dOff; \
        const int ko = (kc) * 32; \
        CP_ASYNC16(sb + 0*GT_TILE,      gAh + ko); \
        CP_ASYNC16(sb + 0*GT_TILE + 16, gAh + ko + 8); \
        CP_ASYNC16(sb + 1*GT_TILE,      gAl + ko); \
        CP_ASYNC16(sb + 1*GT_TILE + 16, gAl + ko + 8); \
        CP_ASYNC16(sb + 2*GT_TILE,      gBh + ko); \
        CP_ASYNC16(sb + 2*GT_TILE + 16, gBh + ko + 8); \
        CP_ASYNC16(sb + 3*GT_TILE,      gBl + ko); \
        CP_ASYNC16(sb + 3*GT_TILE + 16, gBl + ko + 8); \
    } while (0)

    // ---- per-lane ldmatrix address components (bytes)
    const uint32_t a_lane = (uint32_t)((lane & 15) * 80 + (lane >> 4) * 16);
    const uint32_t b_lane = (uint32_t)((((lane >> 4) & 1) * 8 + (lane & 7)) * 80
                                       + ((lane >> 3) & 1) * 16);

    float acc[2][8][4];
    #pragma unroll
    for (int mt = 0; mt < 2; mt++)
        #pragma unroll
        for (int nt = 0; nt < 8; nt++)
            #pragma unroll
            for (int j = 0; j < 4; j++) acc[mt][nt][j] = 0.0f;

    LOAD_STAGE(0, 0);
    CP_COMMIT();

    const int NKC = KTOT / 32;   // 32
    for (int kc = 0; kc < NKC; kc++) {
        const int cur = kc & 1;
        if (kc + 1 < NKC) {
            LOAD_STAGE(cur ^ 1, kc + 1);
            CP_COMMIT();
            CP_WAIT(1);
        } else {
            CP_WAIT(0);
        }
        __syncthreads();

        const uint32_t aB = smb + cur * GT_STAGE + (uint32_t)(wr * 32 * 80) + a_lane;
        const uint32_t bB = smb + cur * GT_STAGE + 2 * GT_TILE
                          + (uint32_t)(wc * 64 * 80) + b_lane;
        #pragma unroll
        for (int kk = 0; kk < 2; kk++) {
            uint32_t ah[2][4], al[2][4], bh[8][2], bl[8][2];
            #pragma unroll
            for (int mt = 0; mt < 2; mt++) {
                const uint32_t ao = aB + (uint32_t)(mt * 16 * 80 + kk * 32);
                LDMATRIX_X4(ah[mt][0], ah[mt][1], ah[mt][2], ah[mt][3], ao);
                LDMATRIX_X4(al[mt][0], al[mt][1], al[mt][2], al[mt][3], ao + GT_TILE);
            }
            #pragma unroll
            for (int np = 0; np < 4; np++) {
                const uint32_t bo = bB + (uint32_t)(np * 16 * 80 + kk * 32);
                LDMATRIX_X4(bh[2*np][0], bh[2*np][1], bh[2*np+1][0], bh[2*np+1][1], bo);
                LDMATRIX_X4(bl[2*np][0], bl[2*np][1], bl[2*np+1][0], bl[2*np+1][1],
                            bo + GT_TILE);
            }
            #pragma unroll
            for (int mt = 0; mt < 2; mt++)
                #pragma unroll
                for (int nt = 0; nt < 8; nt++) {
                    MMA_BF16(acc[mt][nt], ah[mt], bh[nt]);
                    MMA_BF16(acc[mt][nt], ah[mt], bl[nt]);
                    MMA_BF16(acc[mt][nt], al[mt], bh[nt]);
                }
        }
        __syncthreads();
    }

    // ---- epilogue: bias add, route to q/k/v (N-tile never straddles sections)
    const int sec = n0 >> 10;
    float* dst = (sec == 0) ? g_q : (sec == 1) ? g_k : g_v;
    const int ncol = (n0 & 1023) + wc * 64;
    const int gn   = n0 + wc * 64;
    const int r0   = m0 + wr * 32 + (lane >> 2);
    const int c2   = (lane & 3) * 2;
    #pragma unroll
    for (int mt = 0; mt < 2; mt++)
        #pragma unroll
        for (int nt = 0; nt < 8; nt++) {
            const float2 bv = *(const float2*)&bias[gn + nt * 8 + c2];
            const size_t row = (size_t)(r0 + mt * 16);
            float2 v0, v1;
            v0.x = acc[mt][nt][0] + bv.x; v0.y = acc[mt][nt][1] + bv.y;
            v1.x = acc[mt][nt][2] + bv.x; v1.y = acc[mt][nt][3] + bv.y;
            *(float2*)&dst[row * HIDDEN + ncol + nt * 8 + c2] = v0;
            *(float2*)&dst[(row + 8) * HIDDEN + ncol + nt * 8 + c2] = v1;
        }
}

// ---------------------------------------------------------------------------
// In-place RoPE on g_q and g_k
// ---------------------------------------------------------------------------
__global__ void rope_kernel() {
    const int tot = MTOT * NHEAD * 32;
    int idx = blockIdx.x * blockDim.x + threadIdx.x;
    if (idx >= tot) return;
    const int j = idx & 31;
    const int h = (idx >> 5) & 15;
    const int m = idx >> 9;
    const int s = m & (SEQ - 1);
    const float c  = g_cs[(s * 32 + j) * 2 + 0];
    const float sn = g_cs[(s * 32 + j) * 2 + 1];
    const size_t base = (size_t)m * HIDDEN + h * DHEAD + j;

    float q1 = g_q[base], q2 = g_q[base + 32];
    g_q[base]      = q1 * c - q2 * sn;
    g_q[base + 32] = q2 * c + q1 * sn;

    float k1 = g_k[base], k2 = g_k[base + 32];
    g_k[base]      = k1 * c - k2 * sn;
    g_k[base + 32] = k2 * c + k1 * sn;
}

// ---------------------------------------------------------------------------
// Flash attention (fp32 SIMT) — unchanged from R1 baseline
// ---------------------------------------------------------------------------
#define ATTN_SMEM ((4096 + 4096 + 64*68 + 64*68) * 4)

__global__ __launch_bounds__(128) void attn_kernel(float* __restrict__ out) {
    extern __shared__ float smf[];
    float* Qst = smf;                  // [64][64]  Qst[dd*64 + q]
    float* Kst = smf + 4096;           // [64][64]  Kst[dd*64 + k]
    float* Pst = smf + 8192;           // [64][68]  Pst[q*68 + k]
    float* Vs  = smf + 8192 + 64*68;   // [64][68]  Vs[k*68 + dd]

    const int tid = threadIdx.x;
    const int ty  = tid >> 4;
    const int tx  = tid & 15;
    const int bh  = blockIdx.y;
    const int b   = bh >> 4;
    const int h   = bh & 15;
    const int q0  = blockIdx.x * 64;
    const size_t rowbase = (size_t)b * SEQ;
    const float* Qg = g_q + rowbase * HIDDEN + h * DHEAD;
    const float* Kg = g_k + rowbase * HIDDEN + h * DHEAD;
    const float* Vg = g_v + rowbase * HIDDEN + h * DHEAD;

    const int lrow = tid & 63;
    const int half = tid >> 6;

    #pragma unroll
    for (int it = 0; it < 8; it++) {
        const int dd = (it * 2 + half) * 4;
        float4 v = *(const float4*)&Qg[(size_t)(q0 + lrow) * HIDDEN + dd];
        Qst[(dd + 0) * 64 + lrow] = v.x * 0.125f;
        Qst[(dd + 1) * 64 + lrow] = v.y * 0.125f;
        Qst[(dd + 2) * 64 + lrow] = v.z * 0.125f;
        Qst[(dd + 3) * 64 + lrow] = v.w * 0.125f;
    }

    float m_i[8], l_i[8], o[8][4];
    #pragma unroll
    for (int i = 0; i < 8; i++) {
        m_i[i] = -INFINITY; l_i[i] = 0.0f;
        #pragma unroll
        for (int j = 0; j < 4; j++) o[i][j] = 0.0f;
    }

    for (int kt = 0; kt < SEQ / 64; kt++) {
        __syncthreads();

        #pragma unroll
        for (int it = 0; it < 8; it++) {
            const int dd = (it * 2 + half) * 4;
            float4 v = *(const float4*)&Kg[(size_t)(kt * 64 + lrow) * HIDDEN + dd];
            Kst[(dd + 0) * 64 + lrow] = v.x;
            Kst[(dd + 1) * 64 + lrow] = v.y;
            Kst[(dd + 2) * 64 + lrow] = v.z;
            Kst[(dd + 3) * 64 + lrow] = v.w;
        }
        #pragma unroll
        for (int it = 0; it < 8; it++) {
            const int idx = it * 128 + tid;
            const int r = idx >> 4, c = (idx & 15) * 4;
            *(float4*)&Vs[r * 68 + c] =
                *(const float4*)&Vg[(size_t)(kt * 64 + r) * HIDDEN + c];
        }
        __syncthreads();

        float s[8][4];
        #pragma unroll
        for (int i = 0; i < 8; i++)
            #pragma unroll
            for (int j = 0; j < 4; j++) s[i][j] = 0.0f;

        #pragma unroll 8
        for (int dd = 0; dd < 64; dd++) {
            float a[8], bb[4];
            *(float4*)&a[0]  = *(const float4*)&Qst[dd * 64 + ty * 8];
            *(float4*)&a[4]  = *(const float4*)&Qst[dd * 64 + ty * 8 + 4];
            *(float4*)&bb[0] = *(const float4*)&Kst[dd * 64 + tx * 4];
            #pragma unroll
            for (int i = 0; i < 8; i++)
                #pragma unroll
                for (int j = 0; j < 4; j++)
                    s[i][j] += a[i] * bb[j];
        }

        #pragma unroll
        for (int i = 0; i < 8; i++) {
            float mx = fmaxf(fmaxf(s[i][0], s[i][1]), fmaxf(s[i][2], s[i][3]));
            #pragma unroll
            for (int off = 8; off >= 1; off >>= 1)
                mx = fmaxf(mx, __shfl_xor_sync(0xffffffffu, mx, off));
            const float mnew  = fmaxf(m_i[i], mx);
            const float alpha = expf(m_i[i] - mnew);
            float rs = 0.0f;
            #pragma unroll
            for (int j = 0; j < 4; j++) {
                float p = expf(s[i][j] - mnew);
                s[i][j] = p;
                rs += p;
            }
            #pragma unroll
            for (int off = 8; off >= 1; off >>= 1)
                rs += __shfl_xor_sync(0xffffffffu, rs, off);
            l_i[i] = l_i[i] * alpha + rs;
            m_i[i] = mnew;
            #pragma unroll
            for (int j = 0; j < 4; j++) o[i][j] *= alpha;
            *(float4*)&Pst[(ty * 8 + i) * 68 + tx * 4] = *(float4*)&s[i][0];
        }
        __syncthreads();

        #pragma unroll 8
        for (int kk = 0; kk < 64; kk++) {
            float bb[4];
            *(float4*)&bb[0] = *(const float4*)&Vs[kk * 68 + tx * 4];
            #pragma unroll
            for (int i = 0; i < 8; i++) {
                const float a = Pst[(ty * 8 + i) * 68 + kk];
                #pragma unroll
                for (int j = 0; j < 4; j++)
                    o[i][j] += a * bb[j];
            }
        }
    }

    #pragma unroll
    for (int i = 0; i < 8; i++) {
        const float inv = 1.0f / l_i[i];
        float4 v;
        v.x = o[i][0] * inv; v.y = o[i][1] * inv;
        v.z = o[i][2] * inv; v.w = o[i][3] * inv;
        const size_t row = rowbase + q0 + ty * 8 + i;
        *(float4*)&out[row * HIDDEN + h * DHEAD + tx * 4] = v;
    }
}

// ---------------------------------------------------------------------------
extern "C" void kernel_launch(void* const* d_in, const int* in_sizes, int n_in,
                              void* d_out, int out_size) {
    const float* hidden = (const float*)d_in[0];
    const float* wqkv   = (const float*)d_in[1];
    const float* bqkv   = (const float*)d_in[2];
    float* out = (float*)d_out;

    cudaFuncSetAttribute(attn_kernel,
                         cudaFuncAttributeMaxDynamicSharedMemorySize, ATTN_SMEM);
    cudaFuncSetAttribute(qkv_gemm_mma,
                         cudaFuncAttributeMaxDynamicSharedMemorySize, GEMM_SMEM);

    rope_table_kernel<<<(SEQ * 32 + 255) / 256, 256>>>();

    __nv_bfloat16 *ahi, *alo, *whi, *wlo;
    cudaGetSymbolAddress((void**)&ahi, g_ahi);
    cudaGetSymbolAddress((void**)&alo, g_alo);
    cudaGetSymbolAddress((void**)&whi, g_whi);
    cudaGetSymbolAddress((void**)&wlo, g_wlo);

    convert_split_kernel<<<(MTOT*KTOT/4 + 255) / 256, 256>>>(hidden, ahi, alo, MTOT*KTOT/4);
    convert_split_kernel<<<(NTOT*KTOT/4 + 255) / 256, 256>>>(wqkv, whi, wlo, NTOT*KTOT/4);

    dim3 ggrid(NTOT / 128, MTOT / 128);
    qkv_gemm_mma<<<ggrid, 256, GEMM_SMEM>>>(bqkv);

    const int rtot = MTOT * NHEAD * 32;
    rope_kernel<<<rtot / 256, 256>>>();

    dim3 agrid(SEQ / 64, BATCH * NHEAD);
    attn_kernel<<<agrid, 128, ATTN_SMEM>>>(out);
}

// round 6
// speedup vs baseline: 3.2916x; 2.5141x over previous
#include <cuda_runtime.h>
#include <cuda_bf16.h>
#include <cuda_fp16.h>
#include <math.h>
#include <stdint.h>

#define BATCH 4
#define SEQ 2048
#define HIDDEN 1024
#define NHEAD 16
#define DHEAD 64
#define MTOT (BATCH*SEQ)      // 8192
#define NTOT (3*HIDDEN)       // 3072
#define KTOT HIDDEN           // 1024

// ---------------------------------------------------------------------------
// Scratch (device globals)
// ---------------------------------------------------------------------------
__device__ float g_q[(size_t)MTOT*HIDDEN];
__device__ float g_k[(size_t)MTOT*HIDDEN];
__device__ float g_v[(size_t)MTOT*HIDDEN];
__device__ float g_cs[SEQ*32*2];
__device__ __nv_bfloat16 g_ahi[(size_t)MTOT*KTOT];
__device__ __nv_bfloat16 g_alo[(size_t)MTOT*KTOT];
__device__ __nv_bfloat16 g_whi[(size_t)NTOT*KTOT];
__device__ __nv_bfloat16 g_wlo[(size_t)NTOT*KTOT];
// per-head layouts [b*16+h][s][64]
__device__ __nv_bfloat16 g_qh[(size_t)MTOT*HIDDEN];
__device__ __nv_bfloat16 g_ql[(size_t)MTOT*HIDDEN];
__device__ __nv_bfloat16 g_kh[(size_t)MTOT*HIDDEN];
__device__ __nv_bfloat16 g_kl[(size_t)MTOT*HIDDEN];
__device__ __half        g_vh[(size_t)MTOT*HIDDEN];
__device__ __half        g_vl[(size_t)MTOT*HIDDEN];

// ---------------------------------------------------------------------------
// PTX helpers (plain sm_80-era PTX)
// ---------------------------------------------------------------------------
__device__ __forceinline__ uint32_t smem_u32(const void* p) {
    uint32_t a;
    asm("{ .reg .u64 t; cvta.to.shared.u64 t, %1; cvt.u32.u64 %0, t; }"
        : "=r"(a) : "l"(p));
    return a;
}
#define CP_ASYNC16(dst, src) \
    asm volatile("cp.async.cg.shared.global [%0], [%1], 16;" \
        :: "r"(dst), "l"(src))
#define CP_COMMIT() asm volatile("cp.async.commit_group;" ::: "memory")
#define CP_WAIT(n)  asm volatile("cp.async.wait_group %0;" :: "n"(n) : "memory")

#define LDMATRIX_X4(r0, r1, r2, r3, addr) \
    asm volatile("ldmatrix.sync.aligned.m8n8.x4.shared.b16 {%0,%1,%2,%3}, [%4];" \
        : "=r"(r0), "=r"(r1), "=r"(r2), "=r"(r3) : "r"(addr))
#define LDMATRIX_X4_T(r0, r1, r2, r3, addr) \
    asm volatile("ldmatrix.sync.aligned.m8n8.x4.trans.shared.b16 {%0,%1,%2,%3}, [%4];" \
        : "=r"(r0), "=r"(r1), "=r"(r2), "=r"(r3) : "r"(addr))

#define MMA_BF16(d, a, b) \
    asm volatile("mma.sync.aligned.m16n8k16.row.col.f32.bf16.bf16.f32 " \
        "{%0,%1,%2,%3}, {%4,%5,%6,%7}, {%8,%9}, {%0,%1,%2,%3};" \
        : "+f"((d)[0]), "+f"((d)[1]), "+f"((d)[2]), "+f"((d)[3]) \
        : "r"((a)[0]), "r"((a)[1]), "r"((a)[2]), "r"((a)[3]), \
          "r"((b)[0]), "r"((b)[1]))
#define MMA_BF16_B(d, a, b0, b1) \
    asm volatile("mma.sync.aligned.m16n8k16.row.col.f32.bf16.bf16.f32 " \
        "{%0,%1,%2,%3}, {%4,%5,%6,%7}, {%8,%9}, {%0,%1,%2,%3};" \
        : "+f"((d)[0]), "+f"((d)[1]), "+f"((d)[2]), "+f"((d)[3]) \
        : "r"((a)[0]), "r"((a)[1]), "r"((a)[2]), "r"((a)[3]), \
          "r"(b0), "r"(b1))
#define MMA_F16_B(d, a, b0, b1) \
    asm volatile("mma.sync.aligned.m16n8k16.row.col.f32.f16.f16.f32 " \
        "{%0,%1,%2,%3}, {%4,%5,%6,%7}, {%8,%9}, {%0,%1,%2,%3};" \
        : "+f"((d)[0]), "+f"((d)[1]), "+f"((d)[2]), "+f"((d)[3]) \
        : "r"((a)[0]), "r"((a)[1]), "r"((a)[2]), "r"((a)[3]), \
          "r"(b0), "r"(b1))

__device__ __forceinline__ uint32_t packf16(float hi, float lo) {
    uint32_t r;
    asm("cvt.rn.f16x2.f32 %0, %1, %2;" : "=r"(r) : "f"(hi), "f"(lo));
    return r;
}
__device__ __forceinline__ uint32_t ex2x2(uint32_t x) {
    uint32_t r;
    asm("ex2.approx.f16x2 %0, %1;" : "=r"(r) : "r"(x));
    return r;
}
__device__ __forceinline__ float ex2f_(float x) {
    float r;
    asm("ex2.approx.f32 %0, %1;" : "=f"(r) : "f"(x));
    return r;
}

// ---------------------------------------------------------------------------
// RoPE cos/sin table
// ---------------------------------------------------------------------------
__global__ void rope_table_kernel() {
    int idx = blockIdx.x * blockDim.x + threadIdx.x;
    if (idx >= SEQ * 32) return;
    int s = idx >> 5;
    int j = idx & 31;
    float invf = (float)(1.0 / pow(10000.0, (double)j / 32.0));
    float ang  = (float)s * invf;
    g_cs[idx*2 + 0] = (float)cos((double)ang);
    g_cs[idx*2 + 1] = (float)sin((double)ang);
}

// ---------------------------------------------------------------------------
// fp32 -> (bf16 hi, bf16 lo) split for GEMM inputs
// ---------------------------------------------------------------------------
__global__ void convert_split_kernel(const float* __restrict__ src,
                                     __nv_bfloat16* __restrict__ hi,
                                     __nv_bfloat16* __restrict__ lo, int n4) {
    int i = blockIdx.x * blockDim.x + threadIdx.x;
    if (i >= n4) return;
    float4 v = ((const float4*)src)[i];
    __nv_bfloat16 h[4], l[4];
    const float* f = (const float*)&v;
    #pragma unroll
    for (int j = 0; j < 4; j++) {
        h[j] = __float2bfloat16(f[j]);
        l[j] = __float2bfloat16(f[j] - __bfloat162float(h[j]));
    }
    ((uint2*)hi)[i] = *(const uint2*)h;
    ((uint2*)lo)[i] = *(const uint2*)l;
}

// ---------------------------------------------------------------------------
// QKV GEMM via mma.sync bf16 split (unchanged from R3)
// ---------------------------------------------------------------------------
#define GT_TILE  10240
#define GT_STAGE (4*GT_TILE)
#define GEMM_SMEM (2*GT_STAGE)

__global__ __launch_bounds__(256) void qkv_gemm_mma(const float* __restrict__ bias) {
    extern __shared__ char smg[];
    const uint32_t smb = smem_u32(smg);
    const int tid  = threadIdx.x;
    const int lane = tid & 31;
    const int wid  = tid >> 5;
    const int wr   = wid & 3;
    const int wc   = wid >> 2;
    const int n0   = blockIdx.x * 128;
    const int m0   = blockIdx.y * 128;

    const int lrow = tid >> 1;
    const int lcol = (tid & 1) * 16;
    const __nv_bfloat16* gAh = g_ahi + (size_t)(m0 + lrow) * KTOT + lcol;
    const __nv_bfloat16* gAl = g_alo + (size_t)(m0 + lrow) * KTOT + lcol;
    const __nv_bfloat16* gBh = g_whi + (size_t)(n0 + lrow) * KTOT + lcol;
    const __nv_bfloat16* gBl = g_wlo + (size_t)(n0 + lrow) * KTOT + lcol;
    const uint32_t dOff = (uint32_t)(lrow * 80 + lcol * 2);

    #define LOAD_STAGE(st, kc) do { \
        const uint32_t sb = smb + (st) * GT_STAGE + dOff; \
        const int ko = (kc) * 32; \
        CP_ASYNC16(sb + 0*GT_TILE,      gAh + ko); \
        CP_ASYNC16(sb + 0*GT_TILE + 16, gAh + ko + 8); \
        CP_ASYNC16(sb + 1*GT_TILE,      gAl + ko); \
        CP_ASYNC16(sb + 1*GT_TILE + 16, gAl + ko + 8); \
        CP_ASYNC16(sb + 2*GT_TILE,      gBh + ko); \
        CP_ASYNC16(sb + 2*GT_TILE + 16, gBh + ko + 8); \
        CP_ASYNC16(sb + 3*GT_TILE,      gBl + ko); \
        CP_ASYNC16(sb + 3*GT_TILE + 16, gBl + ko + 8); \
    } while (0)

    const uint32_t a_lane = (uint32_t)((lane & 15) * 80 + (lane >> 4) * 16);
    const uint32_t b_lane = (uint32_t)((((lane >> 4) & 1) * 8 + (lane & 7)) * 80
                                       + ((lane >> 3) & 1) * 16);

    float acc[2][8][4];
    #pragma unroll
    for (int mt = 0; mt < 2; mt++)
        #pragma unroll
        for (int nt = 0; nt < 8; nt++)
            #pragma unroll
            for (int j = 0; j < 4; j++) acc[mt][nt][j] = 0.0f;

    LOAD_STAGE(0, 0);
    CP_COMMIT();

    const int NKC = KTOT / 32;
    for (int kc = 0; kc < NKC; kc++) {
        const int cur = kc & 1;
        if (kc + 1 < NKC) {
            LOAD_STAGE(cur ^ 1, kc + 1);
            CP_COMMIT();
            CP_WAIT(1);
        } else {
            CP_WAIT(0);
        }
        __syncthreads();

        const uint32_t aB = smb + cur * GT_STAGE + (uint32_t)(wr * 32 * 80) + a_lane;
        const uint32_t bB = smb + cur * GT_STAGE + 2 * GT_TILE
                          + (uint32_t)(wc * 64 * 80) + b_lane;
        #pragma unroll
        for (int kk = 0; kk < 2; kk++) {
            uint32_t ah[2][4], al[2][4], bh[8][2], bl[8][2];
            #pragma unroll
            for (int mt = 0; mt < 2; mt++) {
                const uint32_t ao = aB + (uint32_t)(mt * 16 * 80 + kk * 32);
                LDMATRIX_X4(ah[mt][0], ah[mt][1], ah[mt][2], ah[mt][3], ao);
                LDMATRIX_X4(al[mt][0], al[mt][1], al[mt][2], al[mt][3], ao + GT_TILE);
            }
            #pragma unroll
            for (int np = 0; np < 4; np++) {
                const uint32_t bo = bB + (uint32_t)(np * 16 * 80 + kk * 32);
                LDMATRIX_X4(bh[2*np][0], bh[2*np][1], bh[2*np+1][0], bh[2*np+1][1], bo);
                LDMATRIX_X4(bl[2*np][0], bl[2*np][1], bl[2*np+1][0], bl[2*np+1][1],
                            bo + GT_TILE);
            }
            #pragma unroll
            for (int mt = 0; mt < 2; mt++)
                #pragma unroll
                for (int nt = 0; nt < 8; nt++) {
                    MMA_BF16(acc[mt][nt], ah[mt], bh[nt]);
                    MMA_BF16(acc[mt][nt], ah[mt], bl[nt]);
                    MMA_BF16(acc[mt][nt], al[mt], bh[nt]);
                }
        }
        __syncthreads();
    }

    const int sec = n0 >> 10;
    float* dst = (sec == 0) ? g_q : (sec == 1) ? g_k : g_v;
    const int ncol = (n0 & 1023) + wc * 64;
    const int gn   = n0 + wc * 64;
    const int r0   = m0 + wr * 32 + (lane >> 2);
    const int c2   = (lane & 3) * 2;
    #pragma unroll
    for (int mt = 0; mt < 2; mt++)
        #pragma unroll
        for (int nt = 0; nt < 8; nt++) {
            const float2 bv = *(const float2*)&bias[gn + nt * 8 + c2];
            const size_t row = (size_t)(r0 + mt * 16);
            float2 v0, v1;
            v0.x = acc[mt][nt][0] + bv.x; v0.y = acc[mt][nt][1] + bv.y;
            v1.x = acc[mt][nt][2] + bv.x; v1.y = acc[mt][nt][3] + bv.y;
            *(float2*)&dst[row * HIDDEN + ncol + nt * 8 + c2] = v0;
            *(float2*)&dst[(row + 8) * HIDDEN + ncol + nt * 8 + c2] = v1;
        }
}

// ---------------------------------------------------------------------------
// RoPE + scale + bf16 split for Q,K -> per-head layout [bh][s][64]
// Q gets the extra log2e/8 factor (base-2 softmax downstream).
// ---------------------------------------------------------------------------
__global__ void qk_rope_split_kernel() {
    int idx = blockIdx.x * blockDim.x + threadIdx.x;
    if (idx >= MTOT * NHEAD * 32) return;
    const int j = idx & 31;
    const int h = (idx >> 5) & 15;
    const int m = idx >> 9;
    const int s = m & (SEQ - 1);
    const int b = m >> 11;
    const float c  = g_cs[(s * 32 + j) * 2 + 0];
    const float sn = g_cs[(s * 32 + j) * 2 + 1];
    const size_t src = (size_t)m * HIDDEN + h * DHEAD + j;
    const size_t dst = ((size_t)(b * NHEAD + h) * SEQ + s) * DHEAD + j;
    const float QS = 0.125f * 1.44269504088896340736f;

    float q1 = g_q[src], q2 = g_q[src + 32];
    float r1 = (q1 * c - q2 * sn) * QS;
    float r2 = (q2 * c + q1 * sn) * QS;
    __nv_bfloat16 h1 = __float2bfloat16(r1);
    __nv_bfloat16 h2 = __float2bfloat16(r2);
    g_qh[dst]      = h1; g_ql[dst]      = __float2bfloat16(r1 - __bfloat162float(h1));
    g_qh[dst + 32] = h2; g_ql[dst + 32] = __float2bfloat16(r2 - __bfloat162float(h2));

    float k1 = g_k[src], k2 = g_k[src + 32];
    float t1 = k1 * c - k2 * sn;
    float t2 = k2 * c + k1 * sn;
    __nv_bfloat16 kh1 = __float2bfloat16(t1);
    __nv_bfloat16 kh2 = __float2bfloat16(t2);
    g_kh[dst]      = kh1; g_kl[dst]      = __float2bfloat16(t1 - __bfloat162float(kh1));
    g_kh[dst + 32] = kh2; g_kl[dst + 32] = __float2bfloat16(t2 - __bfloat162float(kh2));
}

// ---------------------------------------------------------------------------
// fp32 V -> fp16 hi/lo split, per-head layout
// ---------------------------------------------------------------------------
__global__ void v_split_kernel() {
    int idx = blockIdx.x * blockDim.x + threadIdx.x;   // 2 elems per thread
    if (idx >= MTOT * HIDDEN / 2) return;
    const int d2 = idx & 31;
    const int h  = (idx >> 5) & 15;
    const int m  = idx >> 9;
    const int s  = m & (SEQ - 1);
    const int b  = m >> 11;
    const int d  = d2 * 2;
    const size_t src = (size_t)m * HIDDEN + h * DHEAD + d;
    const size_t dst = ((size_t)(b * NHEAD + h) * SEQ + s) * DHEAD + d;
    float2 v = *(const float2*)&g_v[src];
    __half h0 = __float2half(v.x);
    __half h1 = __float2half(v.y);
    __half l0 = __float2half(v.x - __half2float(h0));
    __half l1 = __float2half(v.y - __half2float(h1));
    __half2 hh; hh.x = h0; hh.y = h1;
    __half2 ll; ll.x = l0; ll.y = l1;
    *(__half2*)&g_vh[dst] = hh;
    *(__half2*)&g_vl[dst] = ll;
}

// ---------------------------------------------------------------------------
// Flash attention on mma.sync.
// CTA: 128 Q rows, 8 warps x 16 rows; 64-key tiles, d=64.
// Smem: Q hi/lo (32KB resident) + 2-stage KV (32KB/stage): [KH,KL,VH,VL].
// 128B rows, XOR swizzle chunk^=(row&7).
// ---------------------------------------------------------------------------
#define AT_QH 0u
#define AT_QL 16384u
#define AT_ST 32768u
#define AT_STSZ 32768u
#define ATT_SMEM 98304

__device__ __forceinline__ void ld_rows(uint32_t sbase, const char* gbase,
                                        int tid, int npass) {
    #pragma unroll
    for (int i = 0; i < npass; i++) {     // 32 rows (256 chunks) per pass
        int row = i * 32 + (tid >> 3);
        int c = tid & 7;
        CP_ASYNC16(sbase + (uint32_t)(row * 128 + ((c ^ (row & 7)) * 16)),
                   gbase + row * 128 + c * 16);
    }
}

__global__ __launch_bounds__(256) void attn_mma(float* __restrict__ out) {
    extern __shared__ char sma[];
    const uint32_t smb = smem_u32(sma);
    const int tid  = threadIdx.x;
    const int lane = tid & 31;
    const int w    = tid >> 5;
    const int bh   = blockIdx.y;
    const int q0   = blockIdx.x * 128;
    const size_t hb = (size_t)bh * SEQ * DHEAD;

    const char* Qhp = (const char*)(g_qh + hb + (size_t)q0 * DHEAD);
    const char* Qlp = (const char*)(g_ql + hb + (size_t)q0 * DHEAD);
    const char* Khp = (const char*)(g_kh + hb);
    const char* Klp = (const char*)(g_kl + hb);
    const char* Vhp = (const char*)(g_vh + hb);
    const char* Vlp = (const char*)(g_vl + hb);

    // Q resident load
    ld_rows(smb + AT_QH, Qhp, tid, 4);
    ld_rows(smb + AT_QL, Qlp, tid, 4);
    // KV stage 0 / tile 0
    {
        uint32_t sb = smb + AT_ST;
        ld_rows(sb,          Khp, tid, 2);
        ld_rows(sb + 8192u,  Klp, tid, 2);
        ld_rows(sb + 16384u, Vhp, tid, 2);
        ld_rows(sb + 24576u, Vlp, tid, 2);
    }
    CP_COMMIT();

    // per-lane ldmatrix address components
    const int arow = w * 16 + (lane & 15);
    const uint32_t aBase = smb + AT_QH + (uint32_t)(arow * 128);
    const int axor = arow & 7;
    const int acs  = lane >> 4;
    const int brow = ((lane >> 4) * 8) + (lane & 7);
    const int bcs  = (lane >> 3) & 1;
    const int vro  = (lane & 7) + ((lane >> 3) & 1) * 8;
    const int vcs  = lane >> 4;

    float O[8][4];
    #pragma unroll
    for (int nf = 0; nf < 8; nf++)
        #pragma unroll
        for (int j = 0; j < 4; j++) O[nf][j] = 0.0f;
    float m0 = -INFINITY, m1 = -INFINITY, l0 = 0.0f, l1 = 0.0f;

    const int NT = SEQ / 64;   // 32
    for (int kt = 0; kt < NT; kt++) {
        const int cur = kt & 1;
        if (kt + 1 < NT) {
            uint32_t sb = smb + AT_ST + (uint32_t)(cur ^ 1) * AT_STSZ;
            const size_t ko = (size_t)(kt + 1) * 64 * 128;   // bytes
            ld_rows(sb,          Khp + ko, tid, 2);
            ld_rows(sb + 8192u,  Klp + ko, tid, 2);
            ld_rows(sb + 16384u, Vhp + ko, tid, 2);
            ld_rows(sb + 24576u, Vlp + ko, tid, 2);
            CP_COMMIT();
            CP_WAIT(1);
        } else {
            CP_WAIT(0);
        }
        __syncthreads();
        const uint32_t stg = smb + AT_ST + (uint32_t)cur * AT_STSZ;

        // ---- S = Q K^T (3-term bf16 split, log2-scaled)
        float S[8][4];
        #pragma unroll
        for (int nf = 0; nf < 8; nf++)
            #pragma unroll
            for (int j = 0; j < 4; j++) S[nf][j] = 0.0f;

        #pragma unroll
        for (int ks = 0; ks < 4; ks++) {
            uint32_t qh_[4], ql_[4];
            const uint32_t aoff = (uint32_t)(((2 * ks + acs) ^ axor) * 16);
            LDMATRIX_X4(qh_[0], qh_[1], qh_[2], qh_[3], aBase + aoff);
            LDMATRIX_X4(ql_[0], ql_[1], ql_[2], ql_[3], aBase + 16384u + aoff);
            #pragma unroll
            for (int ng = 0; ng < 4; ng++) {
                const int rowb = ng * 16 + brow;
                const uint32_t koff = stg + (uint32_t)(rowb * 128
                                   + (((2 * ks + bcs) ^ (rowb & 7)) * 16));
                uint32_t kh_[4], kl_[4];
                LDMATRIX_X4(kh_[0], kh_[1], kh_[2], kh_[3], koff);
                LDMATRIX_X4(kl_[0], kl_[1], kl_[2], kl_[3], koff + 8192u);
                MMA_BF16_B(S[2*ng],   qh_, kh_[0], kh_[1]);
                MMA_BF16_B(S[2*ng+1], qh_, kh_[2], kh_[3]);
                MMA_BF16_B(S[2*ng],   qh_, kl_[0], kl_[1]);
                MMA_BF16_B(S[2*ng+1], qh_, kl_[2], kl_[3]);
                MMA_BF16_B(S[2*ng],   ql_, kh_[0], kh_[1]);
                MMA_BF16_B(S[2*ng+1], ql_, kh_[2], kh_[3]);
            }
        }

        // ---- online softmax (base-2)
        float mx0 = S[0][0], mx1 = S[0][2];
        #pragma unroll
        for (int nf = 0; nf < 8; nf++) {
            mx0 = fmaxf(mx0, fmaxf(S[nf][0], S[nf][1]));
            mx1 = fmaxf(mx1, fmaxf(S[nf][2], S[nf][3]));
        }
        mx0 = fmaxf(mx0, __shfl_xor_sync(0xffffffffu, mx0, 1));
        mx0 = fmaxf(mx0, __shfl_xor_sync(0xffffffffu, mx0, 2));
        mx1 = fmaxf(mx1, __shfl_xor_sync(0xffffffffu, mx1, 1));
        mx1 = fmaxf(mx1, __shfl_xor_sync(0xffffffffu, mx1, 2));
        const float mn0 = fmaxf(m0, mx0);
        const float mn1 = fmaxf(m1, mx1);
        const float a0 = ex2f_(m0 - mn0);
        const float a1 = ex2f_(m1 - mn1);
        m0 = mn0; m1 = mn1;

        uint32_t P[16];
        float s0 = 0.0f, s1 = 0.0f;
        #pragma unroll
        for (int nf = 0; nf < 8; nf++) {
            uint32_t pa = ex2x2(packf16(S[nf][1] - mn0, S[nf][0] - mn0));
            uint32_t pb = ex2x2(packf16(S[nf][3] - mn1, S[nf][2] - mn1));
            P[2*nf]   = pa;
            P[2*nf+1] = pb;
            const __half2 ha = *(const __half2*)&pa;
            const __half2 hbv = *(const __half2*)&pb;
            s0 += __low2float(ha) + __high2float(ha);
            s1 += __low2float(hbv) + __high2float(hbv);
        }
        s0 += __shfl_xor_sync(0xffffffffu, s0, 1);
        s0 += __shfl_xor_sync(0xffffffffu, s0, 2);
        s1 += __shfl_xor_sync(0xffffffffu, s1, 1);
        s1 += __shfl_xor_sync(0xffffffffu, s1, 2);
        l0 = l0 * a0 + s0;
        l1 = l1 * a1 + s1;
        #pragma unroll
        for (int nf = 0; nf < 8; nf++) {
            O[nf][0] *= a0; O[nf][1] *= a0;
            O[nf][2] *= a1; O[nf][3] *= a1;
        }

        // ---- O += P V (fp16, 2-term V split)
        #pragma unroll
        for (int kp = 0; kp < 4; kp++) {
            const uint32_t* Pa = &P[4 * kp];
            #pragma unroll
            for (int g = 0; g < 4; g++) {
                const int rowv = kp * 16 + vro;
                const uint32_t voff = stg + 16384u + (uint32_t)(rowv * 128
                                    + (((2 * g + vcs) ^ (rowv & 7)) * 16));
                uint32_t vh_[4], vl_[4];
                LDMATRIX_X4_T(vh_[0], vh_[1], vh_[2], vh_[3], voff);
                LDMATRIX_X4_T(vl_[0], vl_[1], vl_[2], vl_[3], voff + 8192u);
                MMA_F16_B(O[2*g],   Pa, vh_[0], vh_[1]);
                MMA_F16_B(O[2*g+1], Pa, vh_[2], vh_[3]);
                MMA_F16_B(O[2*g],   Pa, vl_[0], vl_[1]);
                MMA_F16_B(O[2*g+1], Pa, vl_[2], vl_[3]);
            }
        }
        __syncthreads();
    }

    // ---- epilogue
    const float i0 = 1.0f / l0;
    const float i1 = 1.0f / l1;
    const int b = bh >> 4;
    const int h = bh & 15;
    const int row = q0 + w * 16 + (lane >> 2);
    const size_t ob = ((size_t)b * SEQ + row) * HIDDEN + h * DHEAD + (lane & 3) * 2;
    #pragma unroll
    for (int nf = 0; nf < 8; nf++) {
        float2 v0, v1;
        v0.x = O[nf][0] * i0; v0.y = O[nf][1] * i0;
        v1.x = O[nf][2] * i1; v1.y = O[nf][3] * i1;
        *(float2*)&out[ob + nf * 8] = v0;
        *(float2*)&out[ob + 8 * HIDDEN + nf * 8] = v1;
    }
}

// ---------------------------------------------------------------------------
extern "C" void kernel_launch(void* const* d_in, const int* in_sizes, int n_in,
                              void* d_out, int out_size) {
    const float* hidden = (const float*)d_in[0];
    const float* wqkv   = (const float*)d_in[1];
    const float* bqkv   = (const float*)d_in[2];
    float* out = (float*)d_out;

    cudaFuncSetAttribute(qkv_gemm_mma,
                         cudaFuncAttributeMaxDynamicSharedMemorySize, GEMM_SMEM);
    cudaFuncSetAttribute(attn_mma,
                         cudaFuncAttributeMaxDynamicSharedMemorySize, ATT_SMEM);

    rope_table_kernel<<<(SEQ * 32 + 255) / 256, 256>>>();

    __nv_bfloat16 *ahi, *alo, *whi, *wlo;
    cudaGetSymbolAddress((void**)&ahi, g_ahi);
    cudaGetSymbolAddress((void**)&alo, g_alo);
    cudaGetSymbolAddress((void**)&whi, g_whi);
    cudaGetSymbolAddress((void**)&wlo, g_wlo);

    convert_split_kernel<<<(MTOT*KTOT/4 + 255) / 256, 256>>>(hidden, ahi, alo, MTOT*KTOT/4);
    convert_split_kernel<<<(NTOT*KTOT/4 + 255) / 256, 256>>>(wqkv, whi, wlo, NTOT*KTOT/4);

    dim3 ggrid(NTOT / 128, MTOT / 128);
    qkv_gemm_mma<<<ggrid, 256, GEMM_SMEM>>>(bqkv);

    qk_rope_split_kernel<<<(MTOT * NHEAD * 32) / 256, 256>>>();
    v_split_kernel<<<(MTOT * HIDDEN / 2) / 256, 256>>>();

    dim3 agrid(SEQ / 128, BATCH * NHEAD);
    attn_mma<<<agrid, 256, ATT_SMEM>>>(out);
}

// round 7
// speedup vs baseline: 3.4644x; 1.0525x over previous
#include <cuda_runtime.h>
#include <cuda_bf16.h>
#include <cuda_fp16.h>
#include <math.h>
#include <stdint.h>

#define BATCH 4
#define SEQ 2048
#define HIDDEN 1024
#define NHEAD 16
#define DHEAD 64
#define MTOT (BATCH*SEQ)      // 8192
#define NTOT (3*HIDDEN)       // 3072
#define KTOT HIDDEN           // 1024

// ---------------------------------------------------------------------------
// Scratch (device globals)
// ---------------------------------------------------------------------------
__device__ float g_cs[SEQ*32*2];
__device__ __nv_bfloat16 g_ahi[(size_t)MTOT*KTOT];
__device__ __nv_bfloat16 g_alo[(size_t)MTOT*KTOT];
__device__ __nv_bfloat16 g_whi[(size_t)NTOT*KTOT];
__device__ __nv_bfloat16 g_wlo[(size_t)NTOT*KTOT];
// per-head layouts [b*16+h][s][64]
__device__ __nv_bfloat16 g_qh[(size_t)MTOT*HIDDEN];
__device__ __nv_bfloat16 g_ql[(size_t)MTOT*HIDDEN];
__device__ __nv_bfloat16 g_kh[(size_t)MTOT*HIDDEN];
__device__ __nv_bfloat16 g_kl[(size_t)MTOT*HIDDEN];
__device__ __half        g_vh[(size_t)MTOT*HIDDEN];
__device__ __half        g_vl[(size_t)MTOT*HIDDEN];

// ---------------------------------------------------------------------------
// PTX helpers (plain sm_80-era PTX)
// ---------------------------------------------------------------------------
__device__ __forceinline__ uint32_t smem_u32(const void* p) {
    uint32_t a;
    asm("{ .reg .u64 t; cvta.to.shared.u64 t, %1; cvt.u32.u64 %0, t; }"
        : "=r"(a) : "l"(p));
    return a;
}
#define CP_ASYNC16(dst, src) \
    asm volatile("cp.async.cg.shared.global [%0], [%1], 16;" \
        :: "r"(dst), "l"(src))
#define CP_COMMIT() asm volatile("cp.async.commit_group;" ::: "memory")
#define CP_WAIT(n)  asm volatile("cp.async.wait_group %0;" :: "n"(n) : "memory")

#define LDMATRIX_X4(r0, r1, r2, r3, addr) \
    asm volatile("ldmatrix.sync.aligned.m8n8.x4.shared.b16 {%0,%1,%2,%3}, [%4];" \
        : "=r"(r0), "=r"(r1), "=r"(r2), "=r"(r3) : "r"(addr))
#define LDMATRIX_X4_T(r0, r1, r2, r3, addr) \
    asm volatile("ldmatrix.sync.aligned.m8n8.x4.trans.shared.b16 {%0,%1,%2,%3}, [%4];" \
        : "=r"(r0), "=r"(r1), "=r"(r2), "=r"(r3) : "r"(addr))

#define MMA_BF16(d, a, b) \
    asm volatile("mma.sync.aligned.m16n8k16.row.col.f32.bf16.bf16.f32 " \
        "{%0,%1,%2,%3}, {%4,%5,%6,%7}, {%8,%9}, {%0,%1,%2,%3};" \
        : "+f"((d)[0]), "+f"((d)[1]), "+f"((d)[2]), "+f"((d)[3]) \
        : "r"((a)[0]), "r"((a)[1]), "r"((a)[2]), "r"((a)[3]), \
          "r"((b)[0]), "r"((b)[1]))
#define MMA_BF16_B(d, a, b0, b1) \
    asm volatile("mma.sync.aligned.m16n8k16.row.col.f32.bf16.bf16.f32 " \
        "{%0,%1,%2,%3}, {%4,%5,%6,%7}, {%8,%9}, {%0,%1,%2,%3};" \
        : "+f"((d)[0]), "+f"((d)[1]), "+f"((d)[2]), "+f"((d)[3]) \
        : "r"((a)[0]), "r"((a)[1]), "r"((a)[2]), "r"((a)[3]), \
          "r"(b0), "r"(b1))
#define MMA_F16_B(d, a, b0, b1) \
    asm volatile("mma.sync.aligned.m16n8k16.row.col.f32.f16.f16.f32 " \
        "{%0,%1,%2,%3}, {%4,%5,%6,%7}, {%8,%9}, {%0,%1,%2,%3};" \
        : "+f"((d)[0]), "+f"((d)[1]), "+f"((d)[2]), "+f"((d)[3]) \
        : "r"((a)[0]), "r"((a)[1]), "r"((a)[2]), "r"((a)[3]), \
          "r"(b0), "r"(b1))

__device__ __forceinline__ uint32_t packf16(float hi, float lo) {
    uint32_t r;
    asm("cvt.rn.f16x2.f32 %0, %1, %2;" : "=r"(r) : "f"(hi), "f"(lo));
    return r;
}
__device__ __forceinline__ uint32_t ex2x2(uint32_t x) {
    uint32_t r;
    asm("ex2.approx.f16x2 %0, %1;" : "=r"(r) : "r"(x));
    return r;
}
__device__ __forceinline__ float ex2f_(float x) {
    float r;
    asm("ex2.approx.f32 %0, %1;" : "=f"(r) : "f"(x));
    return r;
}

// ---------------------------------------------------------------------------
// RoPE cos/sin table
// ---------------------------------------------------------------------------
__global__ void rope_table_kernel() {
    int idx = blockIdx.x * blockDim.x + threadIdx.x;
    if (idx >= SEQ * 32) return;
    int s = idx >> 5;
    int j = idx & 31;
    float invf = (float)(1.0 / pow(10000.0, (double)j / 32.0));
    float ang  = (float)s * invf;
    g_cs[idx*2 + 0] = (float)cos((double)ang);
    g_cs[idx*2 + 1] = (float)sin((double)ang);
}

// ---------------------------------------------------------------------------
// fp32 -> (bf16 hi, bf16 lo) split for GEMM inputs
// ---------------------------------------------------------------------------
__global__ void convert_split_kernel(const float* __restrict__ src,
                                     __nv_bfloat16* __restrict__ hi,
                                     __nv_bfloat16* __restrict__ lo, int n4) {
    int i = blockIdx.x * blockDim.x + threadIdx.x;
    if (i >= n4) return;
    float4 v = ((const float4*)src)[i];
    __nv_bfloat16 h[4], l[4];
    const float* f = (const float*)&v;
    #pragma unroll
    for (int j = 0; j < 4; j++) {
        h[j] = __float2bfloat16(f[j]);
        l[j] = __float2bfloat16(f[j] - __bfloat162float(h[j]));
    }
    ((uint2*)hi)[i] = *(const uint2*)h;
    ((uint2*)lo)[i] = *(const uint2*)l;
}

// ---------------------------------------------------------------------------
// QKV GEMM via mma.sync bf16 split, FUSED epilogue:
//   bias add + RoPE (q,k) + q-scale + bf16/fp16 hi-lo splitting, written
//   straight to per-head layouts. RoPE pair (j, j+32) = acc[..][nt]/acc[..][nt+4]
//   (thread-local; warp's 64-col tile == one head).
// Mainloop: term-major MMA order, single __syncthreads per k-chunk.
// ---------------------------------------------------------------------------
#define GT_TILE  10240
#define GT_STAGE (4*GT_TILE)
#define GEMM_SMEM (2*GT_STAGE)

__global__ __launch_bounds__(256, 2) void qkv_gemm_mma(const float* __restrict__ bias) {
    extern __shared__ char smg[];
    const uint32_t smb = smem_u32(smg);
    const int tid  = threadIdx.x;
    const int lane = tid & 31;
    const int wid  = tid >> 5;
    const int wr   = wid & 3;
    const int wc   = wid >> 2;
    const int n0   = blockIdx.x * 128;
    const int m0   = blockIdx.y * 128;

    const int lrow = tid >> 1;
    const int lcol = (tid & 1) * 16;
    const __nv_bfloat16* gAh = g_ahi + (size_t)(m0 + lrow) * KTOT + lcol;
    const __nv_bfloat16* gAl = g_alo + (size_t)(m0 + lrow) * KTOT + lcol;
    const __nv_bfloat16* gBh = g_whi + (size_t)(n0 + lrow) * KTOT + lcol;
    const __nv_bfloat16* gBl = g_wlo + (size_t)(n0 + lrow) * KTOT + lcol;
    const uint32_t dOff = (uint32_t)(lrow * 80 + lcol * 2);

    #define LOAD_STAGE(st, kc) do { \
        const uint32_t sb = smb + (st) * GT_STAGE + dOff; \
        const int ko = (kc) * 32; \
        CP_ASYNC16(sb + 0*GT_TILE,      gAh + ko); \
        CP_ASYNC16(sb + 0*GT_TILE + 16, gAh + ko + 8); \
        CP_ASYNC16(sb + 1*GT_TILE,      gAl + ko); \
        CP_ASYNC16(sb + 1*GT_TILE + 16, gAl + ko + 8); \
        CP_ASYNC16(sb + 2*GT_TILE,      gBh + ko); \
        CP_ASYNC16(sb + 2*GT_TILE + 16, gBh + ko + 8); \
        CP_ASYNC16(sb + 3*GT_TILE,      gBl + ko); \
        CP_ASYNC16(sb + 3*GT_TILE + 16, gBl + ko + 8); \
    } while (0)

    const uint32_t a_lane = (uint32_t)((lane & 15) * 80 + (lane >> 4) * 16);
    const uint32_t b_lane = (uint32_t)((((lane >> 4) & 1) * 8 + (lane & 7)) * 80
                                       + ((lane >> 3) & 1) * 16);

    float acc[2][8][4];
    #pragma unroll
    for (int mt = 0; mt < 2; mt++)
        #pragma unroll
        for (int nt = 0; nt < 8; nt++)
            #pragma unroll
            for (int j = 0; j < 4; j++) acc[mt][nt][j] = 0.0f;

    LOAD_STAGE(0, 0);
    CP_COMMIT();

    const int NKC = KTOT / 32;
    for (int kc = 0; kc < NKC; kc++) {
        const int cur = kc & 1;
        CP_WAIT(0);
        __syncthreads();
        if (kc + 1 < NKC) {
            LOAD_STAGE(cur ^ 1, kc + 1);
            CP_COMMIT();
        }

        const uint32_t aB = smb + cur * GT_STAGE + (uint32_t)(wr * 32 * 80) + a_lane;
        const uint32_t bB = smb + cur * GT_STAGE + 2 * GT_TILE
                          + (uint32_t)(wc * 64 * 80) + b_lane;
        #pragma unroll
        for (int kk = 0; kk < 2; kk++) {
            uint32_t ah[2][4], al[2][4], bh[8][2], bl[8][2];
            #pragma unroll
            for (int mt = 0; mt < 2; mt++) {
                const uint32_t ao = aB + (uint32_t)(mt * 16 * 80 + kk * 32);
                LDMATRIX_X4(ah[mt][0], ah[mt][1], ah[mt][2], ah[mt][3], ao);
                LDMATRIX_X4(al[mt][0], al[mt][1], al[mt][2], al[mt][3], ao + GT_TILE);
            }
            #pragma unroll
            for (int np = 0; np < 4; np++) {
                const uint32_t bo = bB + (uint32_t)(np * 16 * 80 + kk * 32);
                LDMATRIX_X4(bh[2*np][0], bh[2*np][1], bh[2*np+1][0], bh[2*np+1][1], bo);
                LDMATRIX_X4(bl[2*np][0], bl[2*np][1], bl[2*np+1][0], bl[2*np+1][1],
                            bo + GT_TILE);
            }
            // term-major: 16 independent MMAs per pass (no 3-chains per acc)
            #pragma unroll
            for (int mt = 0; mt < 2; mt++)
                #pragma unroll
                for (int nt = 0; nt < 8; nt++)
                    MMA_BF16(acc[mt][nt], ah[mt], bh[nt]);
            #pragma unroll
            for (int mt = 0; mt < 2; mt++)
                #pragma unroll
                for (int nt = 0; nt < 8; nt++)
                    MMA_BF16(acc[mt][nt], ah[mt], bl[nt]);
            #pragma unroll
            for (int mt = 0; mt < 2; mt++)
                #pragma unroll
                for (int nt = 0; nt < 8; nt++)
                    MMA_BF16(acc[mt][nt], al[mt], bh[nt]);
        }
    }

    // ---- fused epilogue: bias + rope + split, per-head layout
    const int sec  = n0 >> 10;                       // 0=q, 1=k, 2=v
    const int head = ((n0 & 1023) >> 6) + wc;        // warp tile == one head
    const int gn   = n0 + wc * 64;
    const int c2   = (lane & 3) * 2;
    const int r0   = m0 + wr * 32 + (lane >> 2);
    const float QS = 0.125f * 1.44269504088896340736f;

    float2 bias2[8];
    #pragma unroll
    for (int nt = 0; nt < 8; nt++)
        bias2[nt] = *(const float2*)&bias[gn + nt * 8 + c2];

    #pragma unroll
    for (int mt = 0; mt < 2; mt++) {
        #pragma unroll
        for (int rh = 0; rh < 2; rh++) {
            const int row = r0 + mt * 16 + rh * 8;
            const int s = row & (SEQ - 1);
            const int b = row >> 11;
            const size_t base = ((size_t)(b * NHEAD + head) * SEQ + s) * DHEAD;
            if (sec < 2) {
                __nv_bfloat16* dh = (sec == 0) ? g_qh : g_kh;
                __nv_bfloat16* dl = (sec == 0) ? g_ql : g_kl;
                const float sc = (sec == 0) ? QS : 1.0f;
                #pragma unroll
                for (int nt = 0; nt < 4; nt++) {
                    const int j = nt * 8 + c2;
                    const float4 cs = *(const float4*)&g_cs[(s * 32 + j) * 2];
                    __nv_bfloat16 h1[2], l1[2], h2[2], l2[2];
                    #pragma unroll
                    for (int k = 0; k < 2; k++) {
                        const float x1 = acc[mt][nt][2*rh + k]
                                       + ((const float*)&bias2[nt])[k];
                        const float x2 = acc[mt][nt+4][2*rh + k]
                                       + ((const float*)&bias2[nt+4])[k];
                        const float c  = ((const float*)&cs)[2*k];
                        const float sn = ((const float*)&cs)[2*k+1];
                        const float v1 = (x1 * c - x2 * sn) * sc;
                        const float v2 = (x2 * c + x1 * sn) * sc;
                        h1[k] = __float2bfloat16(v1);
                        l1[k] = __float2bfloat16(v1 - __bfloat162float(h1[k]));
                        h2[k] = __float2bfloat16(v2);
                        l2[k] = __float2bfloat16(v2 - __bfloat162float(h2[k]));
                    }
                    *(uint32_t*)&dh[base + j]      = *(uint32_t*)h1;
                    *(uint32_t*)&dl[base + j]      = *(uint32_t*)l1;
                    *(uint32_t*)&dh[base + j + 32] = *(uint32_t*)h2;
                    *(uint32_t*)&dl[base + j + 32] = *(uint32_t*)l2;
                }
            } else {
                #pragma unroll
                for (int nt = 0; nt < 8; nt++) {
                    const int j = nt * 8 + c2;
                    __half hv[2], lv[2];
                    #pragma unroll
                    for (int k = 0; k < 2; k++) {
                        const float x = acc[mt][nt][2*rh + k]
                                      + ((const float*)&bias2[nt])[k];
                        hv[k] = __float2half(x);
                        lv[k] = __float2half(x - __half2float(hv[k]));
                    }
                    *(uint32_t*)&g_vh[base + j] = *(uint32_t*)hv;
                    *(uint32_t*)&g_vl[base + j] = *(uint32_t*)lv;
                }
            }
        }
    }
}

// ---------------------------------------------------------------------------
// Flash attention on mma.sync (single-sync pipeline).
// CTA: 128 Q rows, 8 warps x 16 rows; 64-key tiles, d=64.
// ---------------------------------------------------------------------------
#define AT_QH 0u
#define AT_QL 16384u
#define AT_ST 32768u
#define AT_STSZ 32768u
#define ATT_SMEM 98304

__device__ __forceinline__ void ld_rows(uint32_t sbase, const char* gbase,
                                        int tid, int npass) {
    #pragma unroll
    for (int i = 0; i < npass; i++) {     // 32 rows (256 chunks) per pass
        int row = i * 32 + (tid >> 3);
        int c = tid & 7;
        CP_ASYNC16(sbase + (uint32_t)(row * 128 + ((c ^ (row & 7)) * 16)),
                   gbase + row * 128 + c * 16);
    }
}

__global__ __launch_bounds__(256) void attn_mma(float* __restrict__ out) {
    extern __shared__ char sma[];
    const uint32_t smb = smem_u32(sma);
    const int tid  = threadIdx.x;
    const int lane = tid & 31;
    const int w    = tid >> 5;
    const int bh   = blockIdx.y;
    const int q0   = blockIdx.x * 128;
    const size_t hb = (size_t)bh * SEQ * DHEAD;

    const char* Qhp = (const char*)(g_qh + hb + (size_t)q0 * DHEAD);
    const char* Qlp = (const char*)(g_ql + hb + (size_t)q0 * DHEAD);
    const char* Khp = (const char*)(g_kh + hb);
    const char* Klp = (const char*)(g_kl + hb);
    const char* Vhp = (const char*)(g_vh + hb);
    const char* Vlp = (const char*)(g_vl + hb);

    // Q resident + KV stage 0
    ld_rows(smb + AT_QH, Qhp, tid, 4);
    ld_rows(smb + AT_QL, Qlp, tid, 4);
    {
        uint32_t sb = smb + AT_ST;
        ld_rows(sb,          Khp, tid, 2);
        ld_rows(sb + 8192u,  Klp, tid, 2);
        ld_rows(sb + 16384u, Vhp, tid, 2);
        ld_rows(sb + 24576u, Vlp, tid, 2);
    }
    CP_COMMIT();

    const int arow = w * 16 + (lane & 15);
    const uint32_t aBase = smb + AT_QH + (uint32_t)(arow * 128);
    const int axor = arow & 7;
    const int acs  = lane >> 4;
    const int brow = ((lane >> 4) * 8) + (lane & 7);
    const int bcs  = (lane >> 3) & 1;
    const int vro  = (lane & 7) + ((lane >> 3) & 1) * 8;
    const int vcs  = lane >> 4;

    float O[8][4];
    #pragma unroll
    for (int nf = 0; nf < 8; nf++)
        #pragma unroll
        for (int j = 0; j < 4; j++) O[nf][j] = 0.0f;
    float m0 = -INFINITY, m1 = -INFINITY, l0 = 0.0f, l1 = 0.0f;

    const int NT = SEQ / 64;   // 32
    for (int kt = 0; kt < NT; kt++) {
        const int cur = kt & 1;
        CP_WAIT(0);
        __syncthreads();
        if (kt + 1 < NT) {
            uint32_t sb = smb + AT_ST + (uint32_t)(cur ^ 1) * AT_STSZ;
            const size_t ko = (size_t)(kt + 1) * 64 * 128;   // bytes
            ld_rows(sb,          Khp + ko, tid, 2);
            ld_rows(sb + 8192u,  Klp + ko, tid, 2);
            ld_rows(sb + 16384u, Vhp + ko, tid, 2);
            ld_rows(sb + 24576u, Vlp + ko, tid, 2);
            CP_COMMIT();
        }
        const uint32_t stg = smb + AT_ST + (uint32_t)cur * AT_STSZ;

        // ---- S = Q K^T (3-term bf16 split, log2-scaled)
        float S[8][4];
        #pragma unroll
        for (int nf = 0; nf < 8; nf++)
            #pragma unroll
            for (int j = 0; j < 4; j++) S[nf][j] = 0.0f;

        #pragma unroll
        for (int ks = 0; ks < 4; ks++) {
            uint32_t qh_[4], ql_[4];
            const uint32_t aoff = (uint32_t)(((2 * ks + acs) ^ axor) * 16);
            LDMATRIX_X4(qh_[0], qh_[1], qh_[2], qh_[3], aBase + aoff);
            LDMATRIX_X4(ql_[0], ql_[1], ql_[2], ql_[3], aBase + 16384u + aoff);
            #pragma unroll
            for (int ng = 0; ng < 4; ng++) {
                const int rowb = ng * 16 + brow;
                const uint32_t koff = stg + (uint32_t)(rowb * 128
                                   + (((2 * ks + bcs) ^ (rowb & 7)) * 16));
                uint32_t kh_[4], kl_[4];
                LDMATRIX_X4(kh_[0], kh_[1], kh_[2], kh_[3], koff);
                LDMATRIX_X4(kl_[0], kl_[1], kl_[2], kl_[3], koff + 8192u);
                MMA_BF16_B(S[2*ng],   qh_, kh_[0], kh_[1]);
                MMA_BF16_B(S[2*ng+1], qh_, kh_[2], kh_[3]);
                MMA_BF16_B(S[2*ng],   qh_, kl_[0], kl_[1]);
                MMA_BF16_B(S[2*ng+1], qh_, kl_[2], kl_[3]);
                MMA_BF16_B(S[2*ng],   ql_, kh_[0], kh_[1]);
                MMA_BF16_B(S[2*ng+1], ql_, kh_[2], kh_[3]);
            }
        }

        // ---- online softmax (base-2)
        float mx0 = S[0][0], mx1 = S[0][2];
        #pragma unroll
        for (int nf = 0; nf < 8; nf++) {
            mx0 = fmaxf(mx0, fmaxf(S[nf][0], S[nf][1]));
            mx1 = fmaxf(mx1, fmaxf(S[nf][2], S[nf][3]));
        }
        mx0 = fmaxf(mx0, __shfl_xor_sync(0xffffffffu, mx0, 1));
        mx0 = fmaxf(mx0, __shfl_xor_sync(0xffffffffu, mx0, 2));
        mx1 = fmaxf(mx1, __shfl_xor_sync(0xffffffffu, mx1, 1));
        mx1 = fmaxf(mx1, __shfl_xor_sync(0xffffffffu, mx1, 2));
        const float mn0 = fmaxf(m0, mx0);
        const float mn1 = fmaxf(m1, mx1);
        const float a0 = ex2f_(m0 - mn0);
        const float a1 = ex2f_(m1 - mn1);
        m0 = mn0; m1 = mn1;

        uint32_t P[16];
        float s0 = 0.0f, s1 = 0.0f;
        #pragma unroll
        for (int nf = 0; nf < 8; nf++) {
            uint32_t pa = ex2x2(packf16(S[nf][1] - mn0, S[nf][0] - mn0));
            uint32_t pb = ex2x2(packf16(S[nf][3] - mn1, S[nf][2] - mn1));
            P[2*nf]   = pa;
            P[2*nf+1] = pb;
            const __half2 ha = *(const __half2*)&pa;
            const __half2 hbv = *(const __half2*)&pb;
            s0 += __low2float(ha) + __high2float(ha);
            s1 += __low2float(hbv) + __high2float(hbv);
        }
        s0 += __shfl_xor_sync(0xffffffffu, s0, 1);
        s0 += __shfl_xor_sync(0xffffffffu, s0, 2);
        s1 += __shfl_xor_sync(0xffffffffu, s1, 1);
        s1 += __shfl_xor_sync(0xffffffffu, s1, 2);
        l0 = l0 * a0 + s0;
        l1 = l1 * a1 + s1;
        #pragma unroll
        for (int nf = 0; nf < 8; nf++) {
            O[nf][0] *= a0; O[nf][1] *= a0;
            O[nf][2] *= a1; O[nf][3] *= a1;
        }

        // ---- O += P V (fp16, 2-term V split)
        #pragma unroll
        for (int kp = 0; kp < 4; kp++) {
            const uint32_t* Pa = &P[4 * kp];
            #pragma unroll
            for (int g = 0; g < 4; g++) {
                const int rowv = kp * 16 + vro;
                const uint32_t voff = stg + 16384u + (uint32_t)(rowv * 128
                                    + (((2 * g + vcs) ^ (rowv & 7)) * 16));
                uint32_t vh_[4], vl_[4];
                LDMATRIX_X4_T(vh_[0], vh_[1], vh_[2], vh_[3], voff);
                LDMATRIX_X4_T(vl_[0], vl_[1], vl_[2], vl_[3], voff + 8192u);
                MMA_F16_B(O[2*g],   Pa, vh_[0], vh_[1]);
                MMA_F16_B(O[2*g+1], Pa, vh_[2], vh_[3]);
                MMA_F16_B(O[2*g],   Pa, vl_[0], vl_[1]);
                MMA_F16_B(O[2*g+1], Pa, vl_[2], vl_[3]);
            }
        }
    }

    // ---- epilogue
    const float i0 = 1.0f / l0;
    const float i1 = 1.0f / l1;
    const int b = bh >> 4;
    const int h = bh & 15;
    const int row = q0 + w * 16 + (lane >> 2);
    const size_t ob = ((size_t)b * SEQ + row) * HIDDEN + h * DHEAD + (lane & 3) * 2;
    #pragma unroll
    for (int nf = 0; nf < 8; nf++) {
        float2 v0, v1;
        v0.x = O[nf][0] * i0; v0.y = O[nf][1] * i0;
        v1.x = O[nf][2] * i1; v1.y = O[nf][3] * i1;
        *(float2*)&out[ob + nf * 8] = v0;
        *(float2*)&out[ob + 8 * HIDDEN + nf * 8] = v1;
    }
}

// ---------------------------------------------------------------------------
extern "C" void kernel_launch(void* const* d_in, const int* in_sizes, int n_in,
                              void* d_out, int out_size) {
    const float* hidden = (const float*)d_in[0];
    const float* wqkv   = (const float*)d_in[1];
    const float* bqkv   = (const float*)d_in[2];
    float* out = (float*)d_out;

    cudaFuncSetAttribute(qkv_gemm_mma,
                         cudaFuncAttributeMaxDynamicSharedMemorySize, GEMM_SMEM);
    cudaFuncSetAttribute(attn_mma,
                         cudaFuncAttributeMaxDynamicSharedMemorySize, ATT_SMEM);

    rope_table_kernel<<<(SEQ * 32 + 255) / 256, 256>>>();

    __nv_bfloat16 *ahi, *alo, *whi, *wlo;
    cudaGetSymbolAddress((void**)&ahi, g_ahi);
    cudaGetSymbolAddress((void**)&alo, g_alo);
    cudaGetSymbolAddress((void**)&whi, g_whi);
    cudaGetSymbolAddress((void**)&wlo, g_wlo);

    convert_split_kernel<<<(MTOT*KTOT/4 + 255) / 256, 256>>>(hidden, ahi, alo, MTOT*KTOT/4);
    convert_split_kernel<<<(NTOT*KTOT/4 + 255) / 256, 256>>>(wqkv, whi, wlo, NTOT*KTOT/4);

    dim3 ggrid(NTOT / 128, MTOT / 128);
    qkv_gemm_mma<<<ggrid, 256, GEMM_SMEM>>>(bqkv);

    dim3 agrid(SEQ / 128, BATCH * NHEAD);
    attn_mma<<<agrid, 256, ATT_SMEM>>>(out);
}